// round 6
// baseline (speedup 1.0000x reference)
#include <cuda_runtime.h>
#include <math.h>

#define NT 100000
#define NB 50
#define NE 1600000
#define NV 15000
#define D  128
#define NPG (NT / NB)          // 2000 nodes per graph
#define SCAN_T 1024
#define SCAN_BLOCKS ((NT + SCAN_T - 1) / SCAN_T)   // 98

// ---------------- static device scratch (no allocations allowed) ----------------
__device__ __align__(16) float g_We1[(size_t)NV * D];  // word_embeds @ W1   7.7 MB
__device__ int   g_count[NT];                          // in-degree / write cursor
__device__ int   g_rowptr[NT + 1];                     // CSR row pointers
__device__ int   g_bsum[SCAN_BLOCKS];
__device__ int   g_boff[SCAN_BLOCKS];
__device__ int   g_col[NE];                            // CSR src per edge (by dst)
__device__ float g_ewe[NE];                            // CSR edge weight
__device__ float g_z[NT];                              // z[n] = lrelu(h1[n]) . u
__device__ float g_h2s[NT];                            // h2[n] . W_out
__device__ __align__(16) float g_u[D];                 // u = W2 @ W_out
__device__ float g_cscal;                              // c = b2 . W_out
__device__ float g_logits[NB];

// ---------------- CSR build ----------------
__global__ void k_zero_count() {
    int i = blockIdx.x * blockDim.x + threadIdx.x;
    if (i < NT) g_count[i] = 0;
}

__global__ void k_count(const int* __restrict__ dst) {
    int stride = gridDim.x * blockDim.x;
    for (int e = blockIdx.x * blockDim.x + threadIdx.x; e < NE; e += stride)
        atomicAdd(&g_count[dst[e]], 1);
}

// per-block inclusive scan -> g_rowptr[i+1] (partial), block totals -> g_bsum
__global__ void k_scanA() {
    __shared__ int sh[SCAN_T];
    int tid = threadIdx.x;
    int i = blockIdx.x * SCAN_T + tid;
    int v = (i < NT) ? g_count[i] : 0;
    sh[tid] = v;
    __syncthreads();
#pragma unroll
    for (int off = 1; off < SCAN_T; off <<= 1) {
        int t = (tid >= off) ? sh[tid - off] : 0;
        __syncthreads();
        sh[tid] += t;
        __syncthreads();
    }
    if (i < NT) g_rowptr[i + 1] = sh[tid];
    if (tid == SCAN_T - 1) g_bsum[blockIdx.x] = sh[tid];
}

// single-block exclusive scan of block sums
__global__ void k_scanB() {
    __shared__ int sh[128];
    int tid = threadIdx.x;
    int v = (tid < SCAN_BLOCKS) ? g_bsum[tid] : 0;
    sh[tid] = v;
    __syncthreads();
#pragma unroll
    for (int off = 1; off < 128; off <<= 1) {
        int t = (tid >= off) ? sh[tid - off] : 0;
        __syncthreads();
        sh[tid] += t;
        __syncthreads();
    }
    if (tid < SCAN_BLOCKS) g_boff[tid] = (tid == 0) ? 0 : sh[tid - 1];
}

__global__ void k_scanC() {
    int tid = threadIdx.x;
    int i = blockIdx.x * SCAN_T + tid;
    if (i < NT) g_rowptr[i + 1] += g_boff[blockIdx.x];
    if (blockIdx.x == 0 && tid == 0) g_rowptr[0] = 0;
}

__global__ void k_copypos() {
    int i = blockIdx.x * blockDim.x + threadIdx.x;
    if (i < NT) g_count[i] = g_rowptr[i];
}

__global__ void k_scatter(const int* __restrict__ src, const int* __restrict__ dst,
                          const float* __restrict__ ew) {
    int stride = gridDim.x * blockDim.x;
    for (int e = blockIdx.x * blockDim.x + threadIdx.x; e < NE; e += stride) {
        int d = dst[e];
        int p = atomicAdd(&g_count[d], 1);
        g_col[p] = src[e];
        g_ewe[p] = ew[e];
    }
}

// ---------------- We1 = word_embeds @ W1 (warp per row) ----------------
__global__ void k_gemm_we1(const float* __restrict__ emb, const float* __restrict__ W1) {
    int lane = threadIdx.x & 31;
    int warp = (blockIdx.x * blockDim.x + threadIdx.x) >> 5;
    int nw = (gridDim.x * blockDim.x) >> 5;
    for (int row = warp; row < NV; row += nw) {
        float4 h4 = *reinterpret_cast<const float4*>(emb + (size_t)row * D + 4 * lane);
        float4 acc = make_float4(0.f, 0.f, 0.f, 0.f);
#pragma unroll 4
        for (int q = 0; q < 32; ++q) {
            float hx = __shfl_sync(0xffffffffu, h4.x, q);
            float hy = __shfl_sync(0xffffffffu, h4.y, q);
            float hz = __shfl_sync(0xffffffffu, h4.z, q);
            float hw = __shfl_sync(0xffffffffu, h4.w, q);
            float4 w0 = __ldg(reinterpret_cast<const float4*>(W1 + (4 * q + 0) * D + 4 * lane));
            float4 w1 = __ldg(reinterpret_cast<const float4*>(W1 + (4 * q + 1) * D + 4 * lane));
            float4 w2 = __ldg(reinterpret_cast<const float4*>(W1 + (4 * q + 2) * D + 4 * lane));
            float4 w3 = __ldg(reinterpret_cast<const float4*>(W1 + (4 * q + 3) * D + 4 * lane));
            acc.x += hx * w0.x + hy * w1.x + hz * w2.x + hw * w3.x;
            acc.y += hx * w0.y + hy * w1.y + hz * w2.y + hw * w3.y;
            acc.z += hx * w0.z + hy * w1.z + hz * w2.z + hw * w3.z;
            acc.w += hx * w0.w + hy * w1.w + hz * w2.w + hw * w3.w;
        }
        *reinterpret_cast<float4*>(g_We1 + (size_t)row * D + 4 * lane) = acc;
    }
}

// ---------------- u = W2 @ W_out, c = b2 . W_out ----------------
__global__ void k_u(const float* __restrict__ W2, const float* __restrict__ Wout,
                    const float* __restrict__ b2) {
    int i = threadIdx.x;
    if (i < D) {
        float s = 0.f;
        for (int j = 0; j < D; ++j) s += W2[i * D + j] * Wout[j];
        g_u[i] = s;
    }
    if (i == 0) {
        float c = 0.f;
        for (int j = 0; j < D; ++j) c += b2[j] * Wout[j];
        g_cscal = c;
    }
}

// ---------------- layer-1 aggregation + lrelu + dot-u (warp per node) ----------------
__global__ void k_agg1(const int* __restrict__ node_ids, const float* __restrict__ b1) {
    int warp = (blockIdx.x * blockDim.x + threadIdx.x) >> 5;
    int lane = threadIdx.x & 31;
    if (warp >= NT) return;
    int n = warp;
    int beg = g_rowptr[n];
    int end = g_rowptr[n + 1];
    float4 acc = make_float4(0.f, 0.f, 0.f, 0.f);
    float ews = 0.f;
    int e = beg;
    int wid_n = 0; float w_n = 0.f;
    if (e < end) { w_n = g_ewe[e]; wid_n = __ldg(&node_ids[g_col[e]]); }
    while (e < end) {
        int wid = wid_n; float w = w_n;
        int e2 = e + 1;
        if (e2 < end) { w_n = g_ewe[e2]; wid_n = __ldg(&node_ids[g_col[e2]]); }
        float4 v = *reinterpret_cast<const float4*>(g_We1 + (size_t)wid * D + 4 * lane);
        acc.x += w * v.x; acc.y += w * v.y; acc.z += w * v.z; acc.w += w * v.w;
        ews += w;
        e = e2;
    }
    int deg = end - beg;
    float4 h1 = make_float4(0.f, 0.f, 0.f, 0.f);
    if (deg > 0) {
        float inv = 1.0f / (float)deg;
        float4 b4 = *reinterpret_cast<const float4*>(b1 + 4 * lane);
        h1.x = (acc.x + b4.x * ews) * inv;
        h1.y = (acc.y + b4.y * ews) * inv;
        h1.z = (acc.z + b4.z * ews) * inv;
        h1.w = (acc.w + b4.w * ews) * inv;
    }
    // leaky_relu(0.01)
    h1.x = h1.x > 0.f ? h1.x : 0.01f * h1.x;
    h1.y = h1.y > 0.f ? h1.y : 0.01f * h1.y;
    h1.z = h1.z > 0.f ? h1.z : 0.01f * h1.z;
    h1.w = h1.w > 0.f ? h1.w : 0.01f * h1.w;
    float4 u4 = *reinterpret_cast<const float4*>(g_u + 4 * lane);
    float zp = h1.x * u4.x + h1.y * u4.y + h1.z * u4.z + h1.w * u4.w;
#pragma unroll
    for (int o = 16; o > 0; o >>= 1) zp += __shfl_xor_sync(0xffffffffu, zp, o);
    if (lane == 0) g_z[n] = zp;
}

// ---------------- layer-2 scalar aggregation (thread per node) ----------------
__global__ void k_agg2() {
    int n = blockIdx.x * blockDim.x + threadIdx.x;
    if (n >= NT) return;
    int beg = g_rowptr[n];
    int end = g_rowptr[n + 1];
    float t = 0.f, ews = 0.f;
    int e = beg;
    float z_n = 0.f, w_n = 0.f;
    if (e < end) { w_n = g_ewe[e]; z_n = g_z[g_col[e]]; }
    while (e < end) {
        float z = z_n, w = w_n;
        int e2 = e + 1;
        if (e2 < end) { w_n = g_ewe[e2]; z_n = g_z[g_col[e2]]; }
        t += w * z;
        ews += w;
        e = e2;
    }
    int deg = end - beg;
    g_h2s[n] = (deg > 0) ? (t + g_cscal * ews) / (float)deg : 0.f;
}

// ---------------- per-graph mean pool of h2 . W_out ----------------
__global__ void k_pool() {
    __shared__ float sh[256];
    int b = blockIdx.x;
    int tid = threadIdx.x;
    float s = 0.f;
    for (int i = tid; i < NPG; i += 256) s += g_h2s[b * NPG + i];
    sh[tid] = s;
    __syncthreads();
    for (int o = 128; o > 0; o >>= 1) {
        if (tid < o) sh[tid] += sh[tid + o];
        __syncthreads();
    }
    if (tid == 0) g_logits[b] = sh[0] / (float)NPG;
}

// ---------------- loss + sigmoid ----------------
__global__ void k_final(const float* __restrict__ y, const float* __restrict__ b_out,
                        float* __restrict__ out) {
    __shared__ float sh[64];
    int t = threadIdx.x;
    float term = 0.f;
    if (t < NB) {
        float l = g_logits[t] + b_out[0];
        term = fmaxf(l, 0.f) - l * y[t] + log1pf(expf(-fabsf(l)));
        out[1 + t] = 1.0f / (1.0f + expf(-l));
    }
    sh[t] = term;
    __syncthreads();
    for (int o = 32; o > 0; o >>= 1) {
        if (t < o) sh[t] += sh[t + o];
        __syncthreads();
    }
    if (t == 0) out[0] = sh[0] / (float)NB;
}

// ---------------- launch ----------------
extern "C" void kernel_launch(void* const* d_in, const int* in_sizes, int n_in,
                              void* d_out, int out_size) {
    const int*   node_ids = (const int*)  d_in[0];
    const int*   src      = (const int*)  d_in[1];
    const int*   dst      = (const int*)  d_in[2];
    const float* ew       = (const float*)d_in[3];
    const float* y_data   = (const float*)d_in[4];
    const float* embeds   = (const float*)d_in[5];
    const float* W1       = (const float*)d_in[6];
    const float* b1       = (const float*)d_in[7];
    const float* W2       = (const float*)d_in[8];
    const float* b2       = (const float*)d_in[9];
    const float* W_out    = (const float*)d_in[10];
    const float* b_out    = (const float*)d_in[11];
    float* out = (float*)d_out;

    (void)in_sizes; (void)n_in; (void)out_size;

    // CSR build
    k_zero_count<<<(NT + 255) / 256, 256>>>();
    k_count<<<2048, 256>>>(dst);
    k_scanA<<<SCAN_BLOCKS, SCAN_T>>>();
    k_scanB<<<1, 128>>>();
    k_scanC<<<SCAN_BLOCKS, SCAN_T>>>();
    k_copypos<<<(NT + 255) / 256, 256>>>();
    k_scatter<<<2048, 256>>>(src, dst, ew);

    // small precomputes (independent of CSR; order in-stream is fine)
    k_gemm_we1<<<256, 256>>>(embeds, W1);
    k_u<<<1, 128>>>(W2, W_out, b2);

    // layer 1 fused: aggregate + bias + mean + lrelu + dot(u)  (warp per node)
    k_agg1<<<NT / 8, 256>>>(node_ids, b1);

    // layer 2 scalar aggregation
    k_agg2<<<(NT + 255) / 256, 256>>>();

    // pool + loss
    k_pool<<<NB, 256>>>();
    k_final<<<1, 64>>>(y_data, b_out, out);
}

// round 11
// speedup vs baseline: 1.2836x; 1.2836x over previous
#include <cuda_runtime.h>
#include <cuda_fp16.h>
#include <math.h>

#define NT 100000
#define NB 50
#define NE 1600000
#define NV 15000
#define D  128
#define NPG (NT / NB)          // 2000 nodes per graph
#define SCAN_T 1024
#define SCAN_BLOCKS ((NT + SCAN_T - 1) / SCAN_T)   // 98

// ---------------- static device scratch (no allocations allowed) ----------------
__device__ __align__(16) __half g_We1h[(size_t)NV * D]; // fp16 word_embeds @ W1 (3.8 MB)
__device__ int   g_count[NT];                           // in-degree / write cursor
__device__ int   g_rowptr[NT + 1];                      // CSR row pointers
__device__ int   g_bsum[SCAN_BLOCKS];
__device__ int   g_boff[SCAN_BLOCKS];
// packed CSR edge payload: x = word id of src, y = src node idx, z = bits(edge weight)
__device__ __align__(16) uint4 g_edge[NE];              // 25.6 MB
__device__ float g_z[NT];                               // z[n] = lrelu(h1[n]) . u
__device__ __align__(16) float g_u[D];                  // u = W2 @ W_out
__device__ float g_cscal;                               // c = b2 . W_out
__device__ float g_gsum[NB];                            // per-graph sum of h2.W_out

// ---------------- zero counters + graph sums ----------------
__global__ void k_zero() {
    int i = blockIdx.x * blockDim.x + threadIdx.x;
    if (i < NT) g_count[i] = 0;
    if (i < NB) g_gsum[i] = 0.f;
}

__global__ void k_count(const int* __restrict__ dst) {
    int stride = gridDim.x * blockDim.x;
    for (int e = blockIdx.x * blockDim.x + threadIdx.x; e < NE; e += stride)
        atomicAdd(&g_count[dst[e]], 1);
}

// per-block inclusive scan -> g_rowptr[i+1] (partial), block totals -> g_bsum
__global__ void k_scanA() {
    __shared__ int sh[SCAN_T];
    int tid = threadIdx.x;
    int i = blockIdx.x * SCAN_T + tid;
    int v = (i < NT) ? g_count[i] : 0;
    sh[tid] = v;
    __syncthreads();
#pragma unroll
    for (int off = 1; off < SCAN_T; off <<= 1) {
        int t = (tid >= off) ? sh[tid - off] : 0;
        __syncthreads();
        sh[tid] += t;
        __syncthreads();
    }
    if (i < NT) g_rowptr[i + 1] = sh[tid];
    if (tid == SCAN_T - 1) g_bsum[blockIdx.x] = sh[tid];
}

__global__ void k_scanB() {
    __shared__ int sh[128];
    int tid = threadIdx.x;
    int v = (tid < SCAN_BLOCKS) ? g_bsum[tid] : 0;
    sh[tid] = v;
    __syncthreads();
#pragma unroll
    for (int off = 1; off < 128; off <<= 1) {
        int t = (tid >= off) ? sh[tid - off] : 0;
        __syncthreads();
        sh[tid] += t;
        __syncthreads();
    }
    if (tid < SCAN_BLOCKS) g_boff[tid] = (tid == 0) ? 0 : sh[tid - 1];
}

// finalize rowptr AND copy to write cursors (merged old copypos)
__global__ void k_scanC() {
    int tid = threadIdx.x;
    int i = blockIdx.x * SCAN_T + tid;
    if (i < NT) {
        int v = g_rowptr[i + 1] + g_boff[blockIdx.x];
        g_rowptr[i + 1] = v;
        if (i + 1 < NT) g_count[i + 1] = v;
    }
    if (blockIdx.x == 0 && tid == 0) { g_rowptr[0] = 0; g_count[0] = 0; }
}

__global__ void k_scatter(const int* __restrict__ src, const int* __restrict__ dst,
                          const float* __restrict__ ew,
                          const int* __restrict__ node_ids) {
    int stride = gridDim.x * blockDim.x;
    for (int e = blockIdx.x * blockDim.x + threadIdx.x; e < NE; e += stride) {
        int s = src[e];
        int d = dst[e];
        float w = ew[e];
        int wid = __ldg(&node_ids[s]);
        int p = atomicAdd(&g_count[d], 1);
        uint4 pk;
        pk.x = (unsigned)wid;
        pk.y = (unsigned)s;
        pk.z = __float_as_uint(w);
        pk.w = 0u;
        g_edge[p] = pk;
    }
}

// ---------------- We1 = word_embeds @ W1, fp16 out, 4-row register blocking ----------------
__global__ void k_gemm_we1(const float* __restrict__ emb, const float* __restrict__ W1) {
    int lane = threadIdx.x & 31;
    int warp = (blockIdx.x * blockDim.x + threadIdx.x) >> 5;
    int nw = (gridDim.x * blockDim.x) >> 5;
    for (int rb = warp * 4; rb < NV; rb += nw * 4) {
        float4 h[4], acc[4];
#pragma unroll
        for (int r = 0; r < 4; ++r) {
            h[r] = *reinterpret_cast<const float4*>(emb + (size_t)(rb + r) * D + 4 * lane);
            acc[r] = make_float4(0.f, 0.f, 0.f, 0.f);
        }
#pragma unroll 2
        for (int q = 0; q < 32; ++q) {
            float4 w0 = __ldg(reinterpret_cast<const float4*>(W1 + (4 * q + 0) * D + 4 * lane));
            float4 w1 = __ldg(reinterpret_cast<const float4*>(W1 + (4 * q + 1) * D + 4 * lane));
            float4 w2 = __ldg(reinterpret_cast<const float4*>(W1 + (4 * q + 2) * D + 4 * lane));
            float4 w3 = __ldg(reinterpret_cast<const float4*>(W1 + (4 * q + 3) * D + 4 * lane));
#pragma unroll
            for (int r = 0; r < 4; ++r) {
                float hx = __shfl_sync(0xffffffffu, h[r].x, q);
                float hy = __shfl_sync(0xffffffffu, h[r].y, q);
                float hz = __shfl_sync(0xffffffffu, h[r].z, q);
                float hw = __shfl_sync(0xffffffffu, h[r].w, q);
                acc[r].x += hx * w0.x + hy * w1.x + hz * w2.x + hw * w3.x;
                acc[r].y += hx * w0.y + hy * w1.y + hz * w2.y + hw * w3.y;
                acc[r].z += hx * w0.z + hy * w1.z + hz * w2.z + hw * w3.z;
                acc[r].w += hx * w0.w + hy * w1.w + hz * w2.w + hw * w3.w;
            }
        }
#pragma unroll
        for (int r = 0; r < 4; ++r) {
            __half2 h01 = __floats2half2_rn(acc[r].x, acc[r].y);
            __half2 h23 = __floats2half2_rn(acc[r].z, acc[r].w);
            uint2 st;
            st.x = *reinterpret_cast<unsigned*>(&h01);
            st.y = *reinterpret_cast<unsigned*>(&h23);
            *reinterpret_cast<uint2*>(g_We1h + (size_t)(rb + r) * D + 4 * lane) = st;
        }
    }
}

// ---------------- u = W2 @ W_out, c = b2 . W_out ----------------
__global__ void k_u(const float* __restrict__ W2, const float* __restrict__ Wout,
                    const float* __restrict__ b2) {
    int i = threadIdx.x;
    if (i < D) {
        float s = 0.f;
        for (int j = 0; j < D; ++j) s += W2[i * D + j] * Wout[j];
        g_u[i] = s;
    }
    if (i == 0) {
        float c = 0.f;
        for (int j = 0; j < D; ++j) c += b2[j] * Wout[j];
        g_cscal = c;
    }
}

// ---------------- layer-1 aggregation + lrelu + dot-u (warp per node, fp16 rows) ---------
__global__ void k_agg1(const float* __restrict__ b1) {
    int warp = (blockIdx.x * blockDim.x + threadIdx.x) >> 5;
    int lane = threadIdx.x & 31;
    if (warp >= NT) return;
    int n = warp;
    int beg = g_rowptr[n];
    int end = g_rowptr[n + 1];
    float4 acc = make_float4(0.f, 0.f, 0.f, 0.f);
    float ews = 0.f;

    int e = beg;
    uint4 p_cur, p_nxt;
    uint2 r_cur, r_nxt;
    if (e < end) {
        p_cur = __ldg(&g_edge[e]);
        r_cur = __ldg(reinterpret_cast<const uint2*>(g_We1h + (size_t)p_cur.x * D + 4 * lane));
    }
    if (e + 1 < end) {
        p_nxt = __ldg(&g_edge[e + 1]);
        r_nxt = __ldg(reinterpret_cast<const uint2*>(g_We1h + (size_t)p_nxt.x * D + 4 * lane));
    }
    while (e < end) {
        float w = __uint_as_float(p_cur.z);
        __half2 ha = *reinterpret_cast<__half2*>(&r_cur.x);
        __half2 hb = *reinterpret_cast<__half2*>(&r_cur.y);
        float2 fa = __half22float2(ha);
        float2 fb = __half22float2(hb);
        acc.x += w * fa.x; acc.y += w * fa.y;
        acc.z += w * fb.x; acc.w += w * fb.y;
        ews += w;
        ++e;
        p_cur = p_nxt; r_cur = r_nxt;
        if (e + 1 < end) {
            p_nxt = __ldg(&g_edge[e + 1]);
            r_nxt = __ldg(reinterpret_cast<const uint2*>(g_We1h + (size_t)p_nxt.x * D + 4 * lane));
        }
    }
    int deg = end - beg;
    float4 h1 = make_float4(0.f, 0.f, 0.f, 0.f);
    if (deg > 0) {
        float inv = 1.0f / (float)deg;
        float4 b4 = *reinterpret_cast<const float4*>(b1 + 4 * lane);
        h1.x = (acc.x + b4.x * ews) * inv;
        h1.y = (acc.y + b4.y * ews) * inv;
        h1.z = (acc.z + b4.z * ews) * inv;
        h1.w = (acc.w + b4.w * ews) * inv;
    }
    h1.x = h1.x > 0.f ? h1.x : 0.01f * h1.x;
    h1.y = h1.y > 0.f ? h1.y : 0.01f * h1.y;
    h1.z = h1.z > 0.f ? h1.z : 0.01f * h1.z;
    h1.w = h1.w > 0.f ? h1.w : 0.01f * h1.w;
    float4 u4 = *reinterpret_cast<const float4*>(g_u + 4 * lane);
    float zp = h1.x * u4.x + h1.y * u4.y + h1.z * u4.z + h1.w * u4.w;
#pragma unroll
    for (int o = 16; o > 0; o >>= 1) zp += __shfl_xor_sync(0xffffffffu, zp, o);
    if (lane == 0) g_z[n] = zp;
}

// ---------------- layer-2 scalar aggregation + fused per-graph pool ----------------
__global__ void k_agg2pool() {
    __shared__ float sacc[2];
    int tid = threadIdx.x;
    int n = blockIdx.x * blockDim.x + tid;
    int g0 = (blockIdx.x * blockDim.x) / NPG;   // block spans at most 2 graphs (256 < 2000)
    if (tid < 2) sacc[tid] = 0.f;
    __syncthreads();

    float v = 0.f;
    int g = g0;
    if (n < NT) {
        g = n / NPG;
        int beg = g_rowptr[n];
        int end = g_rowptr[n + 1];
        float t = 0.f, ews = 0.f;
        int e = beg;
        uint4 p_cur, p_nxt;
        float z_cur = 0.f, z_nxt = 0.f;
        if (e < end) {
            p_cur = __ldg(&g_edge[e]);
            z_cur = g_z[p_cur.y];
        }
        if (e + 1 < end) {
            p_nxt = __ldg(&g_edge[e + 1]);
            z_nxt = g_z[p_nxt.y];
        }
        while (e < end) {
            float w = __uint_as_float(p_cur.z);
            t += w * z_cur;
            ews += w;
            ++e;
            p_cur = p_nxt; z_cur = z_nxt;
            if (e + 1 < end) {
                p_nxt = __ldg(&g_edge[e + 1]);
                z_nxt = g_z[p_nxt.y];
            }
        }
        int deg = end - beg;
        v = (deg > 0) ? (t + g_cscal * ews) / (float)deg : 0.f;
    }
    // warp-level partial reduce within same graph, then shared atomics
    atomicAdd(&sacc[g - g0], v);
    __syncthreads();
    if (tid < 2) {
        int gg = g0 + tid;
        if (gg < NB && sacc[tid] != 0.f) atomicAdd(&g_gsum[gg], sacc[tid]);
        else if (gg < NB) atomicAdd(&g_gsum[gg], sacc[tid]);  // keep deterministic path
    }
}

// ---------------- loss + sigmoid ----------------
__global__ void k_final(const float* __restrict__ y, const float* __restrict__ b_out,
                        float* __restrict__ out) {
    __shared__ float sh[64];
    int t = threadIdx.x;
    float term = 0.f;
    if (t < NB) {
        float l = g_gsum[t] * (1.0f / (float)NPG) + b_out[0];
        term = fmaxf(l, 0.f) - l * y[t] + log1pf(expf(-fabsf(l)));
        out[1 + t] = 1.0f / (1.0f + expf(-l));
    }
    sh[t] = term;
    __syncthreads();
    for (int o = 32; o > 0; o >>= 1) {
        if (t < o) sh[t] += sh[t + o];
        __syncthreads();
    }
    if (t == 0) out[0] = sh[0] / (float)NB;
}

// ---------------- launch ----------------
extern "C" void kernel_launch(void* const* d_in, const int* in_sizes, int n_in,
                              void* d_out, int out_size) {
    const int*   node_ids = (const int*)  d_in[0];
    const int*   src      = (const int*)  d_in[1];
    const int*   dst      = (const int*)  d_in[2];
    const float* ew       = (const float*)d_in[3];
    const float* y_data   = (const float*)d_in[4];
    const float* embeds   = (const float*)d_in[5];
    const float* W1       = (const float*)d_in[6];
    const float* b1       = (const float*)d_in[7];
    const float* W2       = (const float*)d_in[8];
    const float* b2       = (const float*)d_in[9];
    const float* W_out    = (const float*)d_in[10];
    const float* b_out    = (const float*)d_in[11];
    float* out = (float*)d_out;

    (void)in_sizes; (void)n_in; (void)out_size;

    // small precomputes first (establish We1 in L2 before scatter traffic)
    k_gemm_we1<<<256, 256>>>(embeds, W1);
    k_u<<<1, 128>>>(W2, W_out, b2);

    // CSR build
    k_zero<<<(NT + 255) / 256, 256>>>();
    k_count<<<2048, 256>>>(dst);
    k_scanA<<<SCAN_BLOCKS, SCAN_T>>>();
    k_scanB<<<1, 128>>>();
    k_scanC<<<SCAN_BLOCKS, SCAN_T>>>();
    k_scatter<<<2048, 256>>>(src, dst, ew, node_ids);

    // layer 1 fused: aggregate (fp16 rows) + bias + mean + lrelu + dot(u)
    k_agg1<<<NT / 8, 256>>>(b1);

    // layer 2 scalar aggregation + per-graph pool
    k_agg2pool<<<(NT + 255) / 256, 256>>>();

    // loss + sigmoid
    k_final<<<1, 64>>>(y_data, b_out, out);
}